// round 2
// baseline (speedup 1.0000x reference)
#include <cuda_runtime.h>

#define H 128
#define F 166
#define NMAX 100000
#define EMAX 600000

typedef unsigned int u32;
typedef unsigned long long u64;

// ---------------- scratch (static device memory; no allocs) ----------------
__device__ float g_h[(size_t)NMAX * H];
__device__ float g_r[(size_t)NMAX * H];
__device__ float g_z[(size_t)NMAX * H];
__device__ float g_hc[(size_t)NMAX * H];
__device__ float g_hlrec[(size_t)NMAX * H];
__device__ float g_hlhis[(size_t)NMAX * H];
__device__ float g_aggrec[(size_t)NMAX * H];
__device__ float g_agghis[(size_t)NMAX * H];
__device__ float g_h2[(size_t)NMAX * H];
__device__ float g_v[(size_t)NMAX * H];
__device__ float g_ao[(size_t)NMAX * H];
__device__ float g_h3[(size_t)NMAX * H];
__device__ float g_cls[(size_t)NMAX * 64];
__device__ float g_nt[NMAX];
__device__ u32 g_degrec[NMAX], g_deghis[NMAX];
__device__ float g_disrec[NMAX], g_dishis[NMAX];
__device__ unsigned char g_upd[NMAX];
__device__ u32 g_hist1[65536], g_hist2a[65536], g_hist2b[65536];
__device__ u32 g_offs[NMAX], g_cursor[NMAX], g_bsum[512];
__device__ u32 g_esrc[EMAX];
__device__ float g_ecoef[EMAX];
// scalars: 0 ntmin 1 ntmax 2 bin0 3 rank0 4 bin1 5 rank1
//          6 low0 7 lrank0 8 low1 9 lrank1 10 med_bits
__device__ u32 g_scal[16];

// ---------------- helpers ----------------
__device__ __forceinline__ u64 dup2(float x) {
    u64 r; asm("mov.b64 %0, {%1, %1};" : "=l"(r) : "f"(x)); return r;
}
__device__ __forceinline__ void fma2(u64& d, u64 a, u64 b) {
    asm("fma.rn.f32x2 %0, %1, %2, %0;" : "+l"(d) : "l"(a), "l"(b));
}
__device__ __forceinline__ float2 unpk(u64 v) {
    float2 f; asm("mov.b64 {%0, %1}, %2;" : "=f"(f.x), "=f"(f.y) : "l"(v)); return f;
}
__device__ __forceinline__ float wsum(float v) {
    #pragma unroll
    for (int o = 16; o; o >>= 1) v += __shfl_xor_sync(0xffffffffu, v, o);
    return v;
}
__device__ __forceinline__ float sigmoidf_(float x) { return 1.0f / (1.0f + expf(-x)); }

// ---------------- init ----------------
__global__ void k_init(int N) {
    int tid = blockIdx.x * blockDim.x + threadIdx.x;
    int stride = gridDim.x * blockDim.x;
    for (int i = tid; i < N; i += stride) {
        g_nt[i] = 0.0f; g_upd[i] = 0; g_degrec[i] = 0; g_deghis[i] = 0;
    }
    for (int i = tid; i < 65536; i += stride) {
        g_hist1[i] = 0; g_hist2a[i] = 0; g_hist2b[i] = 0;
    }
    if (tid == 0) { g_scal[0] = 0x7F800000u; g_scal[1] = 0u; }
}

// ---------------- edge pass 1: scatter-max nt, upd flags, median hist lvl1 --
__global__ void k_edge1(const int* __restrict__ ei, const float* __restrict__ ts, int E) {
    int e = blockIdx.x * blockDim.x + threadIdx.x;
    if (e >= E) return;
    int r = ei[e], c = ei[E + e];
    u32 tb = __float_as_uint(ts[e]);
    atomicMax((u32*)&g_nt[c], tb);   // ts >= 0 so bit order == float order
    g_upd[r] = 1; g_upd[c] = 1;
    atomicAdd(&g_hist1[tb >> 16], 1u);
}

// ---------------- min/max over nt ----------------
__global__ void k_minmax(int N) {
    int tid = blockIdx.x * blockDim.x + threadIdx.x;
    int stride = gridDim.x * blockDim.x;
    u32 mn = 0x7F800000u, mx = 0u;
    for (int i = tid; i < N; i += stride) {
        u32 b = __float_as_uint(g_nt[i]);
        mn = min(mn, b); mx = max(mx, b);
    }
    #pragma unroll
    for (int o = 16; o; o >>= 1) {
        mn = min(mn, __shfl_xor_sync(0xffffffffu, mn, o));
        mx = max(mx, __shfl_xor_sync(0xffffffffu, mx, o));
    }
    if ((threadIdx.x & 31) == 0) {
        atomicMin(&g_scal[0], mn);
        atomicMax(&g_scal[1], mx);
    }
}

// ---------------- k-th selection over a 65536-bin histogram ----------------
__global__ void k_select(int which, u32 k_imm, int kidx, int oidx) {
    const u32* hist = (which == 0) ? g_hist1 : (which == 1) ? g_hist2a : g_hist2b;
    __shared__ u32 part[256];
    __shared__ u32 excl[256];
    u32 k = (kidx >= 0) ? g_scal[kidx] : k_imm;
    int t = threadIdx.x;
    u32 s = 0;
    for (int b = 0; b < 256; b++) s += hist[t * 256 + b];
    part[t] = s;
    __syncthreads();
    if (t == 0) {
        u32 run = 0;
        for (int j = 0; j < 256; j++) { excl[j] = run; run += part[j]; }
    }
    __syncthreads();
    u32 base = excl[t];
    if (k >= base && k < base + part[t]) {
        u32 run = base;
        for (int b = 0; b < 256; b++) {
            u32 hv = hist[t * 256 + b];
            if (k < run + hv) { g_scal[oidx] = (u32)(t * 256 + b); g_scal[oidx + 1] = k - run; break; }
            run += hv;
        }
    }
}

// ---------------- median hist level 2 ----------------
__global__ void k_hist2(const float* __restrict__ ts, int E) {
    int e = blockIdx.x * blockDim.x + threadIdx.x;
    if (e >= E) return;
    u32 tb = __float_as_uint(ts[e]);
    u32 hi = tb >> 16;
    if (hi == g_scal[2]) atomicAdd(&g_hist2a[tb & 0xFFFFu], 1u);
    if (hi == g_scal[4]) atomicAdd(&g_hist2b[tb & 0xFFFFu], 1u);
}

__global__ void k_med() {
    float v0 = __uint_as_float((g_scal[2] << 16) | g_scal[6]);
    float v1 = __uint_as_float((g_scal[4] << 16) | g_scal[8]);
    g_scal[10] = __float_as_uint(0.5f * (v0 + v1));
}

// ---------------- per-path in-degree ----------------
__global__ void k_deg(const int* __restrict__ ei, const float* __restrict__ ts, int E) {
    int e = blockIdx.x * blockDim.x + threadIdx.x;
    if (e >= E) return;
    float med = __uint_as_float(g_scal[10]);
    int c = ei[E + e];
    if (ts[e] >= med) atomicAdd(&g_degrec[c], 1u);
    else atomicAdd(&g_deghis[c], 1u);
}

// ---------------- CSR build ----------------
__global__ void k_scan1(int N) {
    __shared__ u32 sh[1024];
    int t = threadIdx.x;
    int i = blockIdx.x * 1024 + t;
    u32 v = (i < N) ? (g_degrec[i] + g_deghis[i]) : 0u;
    sh[t] = v;
    __syncthreads();
    for (int off = 1; off < 1024; off <<= 1) {
        u32 a = (t >= off) ? sh[t - off] : 0u;
        __syncthreads();
        sh[t] += a;
        __syncthreads();
    }
    if (i < N) g_offs[i] = sh[t];             // inclusive within block
    if (t == 1023) g_bsum[blockIdx.x] = sh[1023];
}

__global__ void k_scan2(int NB) {
    if (threadIdx.x == 0) {
        u32 run = 0;
        for (int b = 0; b < NB; b++) { u32 t2 = g_bsum[b]; g_bsum[b] = run; run += t2; }
    }
}

__global__ void k_scan3(int N) {
    int i = blockIdx.x * blockDim.x + threadIdx.x;
    if (i >= N) return;
    u32 cr = g_degrec[i], ch = g_deghis[i];
    u32 excl = g_offs[i] - (cr + ch) + g_bsum[i >> 10];
    g_offs[i] = excl;
    g_cursor[i] = excl;
    g_disrec[i] = rsqrtf((float)cr + 1.0f);
    g_dishis[i] = rsqrtf((float)ch + 1.0f);
}

__global__ void k_fill(const int* __restrict__ ei, const float* __restrict__ ts, int E) {
    int e = blockIdx.x * blockDim.x + threadIdx.x;
    if (e >= E) return;
    float med = __uint_as_float(g_scal[10]);
    int r = ei[e], c = ei[E + e];
    bool rec = ts[e] >= med;
    float coef = rec ? (g_disrec[r] * g_disrec[c]) : (g_dishis[r] * g_dishis[c]);
    u32 p = atomicAdd(&g_cursor[c], 1u);
    g_esrc[p] = ((u32)r << 1) | (rec ? 1u : 0u);
    g_ecoef[p] = coef;
}

// ---------------- fused GEMM: C = epi(A@W^T [+ A2@W2^T]) ----------------
struct Epi {
    const float* bias;
    const float* bias2;
    const float* wtime;
    const float* ex1;
    const float* ex2;
    const float* ex3;
    const float* mem;
    const unsigned char* upd;
    const float* nt;
};

template <int NOUT, int MODE, bool DUAL>
__global__ void k_gemm(const float* __restrict__ A, const float* __restrict__ W,
                       const float* __restrict__ A2, const float* __restrict__ W2,
                       int K, int N, Epi ep, float* __restrict__ C) {
    extern __shared__ float sm[];
    float* As = sm;                    // [K][68]
    const int WST = NOUT + 4;
    float* Ws = sm + (size_t)K * 68;   // [K][NOUT+4]
    const int tx = threadIdx.x;
    const int lane = tx & 31, wp = tx >> 5;
    const int row0 = blockIdx.x * 64;
    constexpr int CPT = NOUT / 32;
    u64 acc[4][CPT];
    #pragma unroll
    for (int p = 0; p < 4; p++)
        #pragma unroll
        for (int n = 0; n < CPT; n++) acc[p][n] = 0ull;

    #pragma unroll
    for (int pass = 0; pass < (DUAL ? 2 : 1); pass++) {
        const float* Ap = pass ? A2 : A;
        const float* Wp = pass ? W2 : W;
        if (pass) __syncthreads();
        for (int idx = tx; idx < 64 * K; idx += 256) {
            int r = idx / K, k = idx - r * K;
            float v = (row0 + r < N) ? Ap[(size_t)(row0 + r) * K + k] : 0.0f;
            As[k * 68 + r] = v;
        }
        for (int idx = tx; idx < NOUT * K; idx += 256) {
            int j = idx / K, k = idx - j * K;
            Ws[k * WST + j] = Wp[idx];
        }
        __syncthreads();
        #pragma unroll 2
        for (int kk = 0; kk < K; kk++) {
            ulonglong2 a01 = *(const ulonglong2*)&As[kk * 68 + wp * 8];
            ulonglong2 a23 = *(const ulonglong2*)&As[kk * 68 + wp * 8 + 4];
            u64 ap[4] = {a01.x, a01.y, a23.x, a23.y};
            float bw[CPT];
            if (CPT == 4) {
                float4 b4 = *(const float4*)&Ws[kk * WST + lane * 4];
                bw[0] = b4.x; bw[1] = b4.y; bw[2] = b4.z; bw[3] = b4.w;
            } else {
                float2 b2 = *(const float2*)&Ws[kk * WST + lane * 2];
                bw[0] = b2.x; bw[1] = b2.y;
            }
            #pragma unroll
            for (int n = 0; n < CPT; n++) {
                u64 bd = dup2(bw[n]);
                #pragma unroll
                for (int p = 0; p < 4; p++) fma2(acc[p][n], ap[p], bd);
            }
        }
    }

    #pragma unroll
    for (int p = 0; p < 4; p++) {
        #pragma unroll
        for (int half = 0; half < 2; half++) {
            int i = row0 + wp * 8 + 2 * p + half;
            if (i >= N) continue;
            #pragma unroll
            for (int n = 0; n < CPT; n++) {
                int c = lane * CPT + n;
                float2 f = unpk(acc[p][n]);
                float v = half ? f.y : f.x;
                if (MODE == 0) {
                    // raw, no bias
                } else if (MODE == 1) {
                    v += ep.bias[c];
                } else if (MODE == 2) {
                    v = fmaxf(v + ep.bias[c], 0.0f);
                } else if (MODE == 3) {
                    v = sigmoidf_(v + ep.bias[c] + ep.bias2[c]);
                } else if (MODE == 4) {
                    float ntv = ep.nt[i];
                    float tmin = __uint_as_float(g_scal[0]);
                    float tmax = __uint_as_float(g_scal[1]);
                    float ntn = (tmax > tmin) ? (ntv - tmin) / (tmax - tmin + 1e-8f) : ntv;
                    v = fmaxf(v + ep.bias[c] + ntn * ep.wtime[c] + ep.bias2[c], 0.0f)
                        + ep.mem[(size_t)i * H + c];
                } else if (MODE == 5) {
                    float hcv = ep.ex1[(size_t)i * NOUT + c];
                    float rv = ep.ex2[(size_t)i * NOUT + c];
                    float zv = ep.ex3[(size_t)i * NOUT + c];
                    float mv = ep.mem[(size_t)i * NOUT + c];
                    float cc = tanhf(v + ep.bias[c] + rv * hcv);
                    v = ep.upd[i] ? ((1.0f - zv) * cc + zv * mv) : mv;
                } else if (MODE == 6) {
                    v += ep.bias[c] + ep.ex1[(size_t)i * NOUT + c];
                }
                C[(size_t)i * NOUT + c] = v;
            }
        }
    }
}

// ---------------- GCN gather (warp per node, both paths at once) -----------
__global__ void k_gather(int N, const float* __restrict__ b_gr, const float* __restrict__ b_gh) {
    int gw = (blockIdx.x * blockDim.x + threadIdx.x) >> 5;
    int lane = threadIdx.x & 31;
    if (gw >= N) return;
    int i = gw;
    u32 start = g_offs[i];
    u32 cnt = g_degrec[i] + g_deghis[i];
    float4 ar = make_float4(0, 0, 0, 0), ah = make_float4(0, 0, 0, 0);
    for (u32 k = start; k < start + cnt; k++) {
        u32 pk = g_esrc[k];
        float cf = g_ecoef[k];
        int s = (int)(pk >> 1);
        if (pk & 1u) {
            float4 v = *(const float4*)&g_hlrec[(size_t)s * H + lane * 4];
            ar.x += v.x * cf; ar.y += v.y * cf; ar.z += v.z * cf; ar.w += v.w * cf;
        } else {
            float4 v = *(const float4*)&g_hlhis[(size_t)s * H + lane * 4];
            ah.x += v.x * cf; ah.y += v.y * cf; ah.z += v.z * cf; ah.w += v.w * cf;
        }
    }
    float fr = g_disrec[i] * g_disrec[i];
    float fh = g_dishis[i] * g_dishis[i];
    float4 sr = *(const float4*)&g_hlrec[(size_t)i * H + lane * 4];
    float4 sh = *(const float4*)&g_hlhis[(size_t)i * H + lane * 4];
    float4 br = *(const float4*)&b_gr[lane * 4];
    float4 bh = *(const float4*)&b_gh[lane * 4];
    float4 outr, outh;
    outr.x = ar.x + sr.x * fr + br.x; outr.y = ar.y + sr.y * fr + br.y;
    outr.z = ar.z + sr.z * fr + br.z; outr.w = ar.w + sr.w * fr + br.w;
    outh.x = ah.x + sh.x * fh + bh.x; outh.y = ah.y + sh.y * fh + bh.y;
    outh.z = ah.z + sh.z * fh + bh.z; outh.w = ah.w + sh.w * fh + bh.w;
    *(float4*)&g_aggrec[(size_t)i * H + lane * 4] = outr;
    *(float4*)&g_agghis[(size_t)i * H + lane * 4] = outh;
}

// ---------------- path softmax mix + LayerNorm (warp per node) -------------
__global__ void k_pathagg(int N, const float* __restrict__ lng, const float* __restrict__ lnb) {
    int gw = (blockIdx.x * blockDim.x + threadIdx.x) >> 5;
    int lane = threadIdx.x & 31;
    if (gw >= N) return;
    int i = gw;
    float4 hr = *(const float4*)&g_aggrec[(size_t)i * H + lane * 4];
    float4 hh = *(const float4*)&g_agghis[(size_t)i * H + lane * 4];
    float s0 = wsum(hr.x + hr.y + hr.z + hr.w) * (1.0f / H);
    float s1 = wsum(hh.x + hh.y + hh.z + hh.w) * (1.0f / H);
    float m = fmaxf(s0, s1);
    float e0 = expf(s0 - m), e1 = expf(s1 - m);
    float w0 = e0 / (e0 + e1), w1 = e1 / (e0 + e1);
    float4 t;
    t.x = hr.x * w0 + hh.x * w1; t.y = hr.y * w0 + hh.y * w1;
    t.z = hr.z * w0 + hh.z * w1; t.w = hr.w * w0 + hh.w * w1;
    float mean = wsum(t.x + t.y + t.z + t.w) * (1.0f / H);
    float4 d;
    d.x = t.x - mean; d.y = t.y - mean; d.z = t.z - mean; d.w = t.w - mean;
    float var = wsum(d.x * d.x + d.y * d.y + d.z * d.z + d.w * d.w) * (1.0f / H);
    float inv = rsqrtf(var + 1e-5f);
    float4 gv = *(const float4*)&lng[lane * 4];
    float4 bv = *(const float4*)&lnb[lane * 4];
    float4 o;
    o.x = d.x * inv * gv.x + bv.x; o.y = d.y * inv * gv.y + bv.y;
    o.z = d.z * inv * gv.z + bv.z; o.w = d.w * inv * gv.w + bv.w;
    *(float4*)&g_h2[(size_t)i * H + lane * 4] = o;
}

// ---------------- plain LayerNorm over g_ao -> g_h3 ----------------
__global__ void k_ln(int N, const float* __restrict__ lng, const float* __restrict__ lnb) {
    int gw = (blockIdx.x * blockDim.x + threadIdx.x) >> 5;
    int lane = threadIdx.x & 31;
    if (gw >= N) return;
    int i = gw;
    float4 t = *(const float4*)&g_ao[(size_t)i * H + lane * 4];
    float mean = wsum(t.x + t.y + t.z + t.w) * (1.0f / H);
    float4 d;
    d.x = t.x - mean; d.y = t.y - mean; d.z = t.z - mean; d.w = t.w - mean;
    float var = wsum(d.x * d.x + d.y * d.y + d.z * d.z + d.w * d.w) * (1.0f / H);
    float inv = rsqrtf(var + 1e-5f);
    float4 gv = *(const float4*)&lng[lane * 4];
    float4 bv = *(const float4*)&lnb[lane * 4];
    float4 o;
    o.x = d.x * inv * gv.x + bv.x; o.y = d.y * inv * gv.y + bv.y;
    o.z = d.z * inv * gv.z + bv.z; o.w = d.w * inv * gv.w + bv.w;
    *(float4*)&g_h3[(size_t)i * H + lane * 4] = o;
}

// ---------------- final tiny classifier layer (warp per node) --------------
__global__ void k_logits(int N, const float* __restrict__ W2, const float* __restrict__ b2,
                         float* __restrict__ out) {
    int gw = (blockIdx.x * blockDim.x + threadIdx.x) >> 5;
    int lane = threadIdx.x & 31;
    if (gw >= N) return;
    int i = gw;
    float v0 = g_cls[(size_t)i * 64 + lane];
    float v1 = g_cls[(size_t)i * 64 + 32 + lane];
    float d0 = v0 * W2[lane] + v1 * W2[32 + lane];
    float d1 = v0 * W2[64 + lane] + v1 * W2[96 + lane];
    d0 = wsum(d0);
    d1 = wsum(d1);
    if (lane == 0) {
        out[(size_t)i * 2 + 0] = d0 + b2[0];
        out[(size_t)i * 2 + 1] = d1 + b2[1];
    }
}

// ---------------- host launcher ----------------
template <int NOUT, int MODE, bool DUAL>
static void gemm_launch(const float* A, const float* W, const float* A2, const float* W2,
                        int K, int N, const Epi& ep, float* C) {
    size_t smem = (size_t)K * 68 * sizeof(float) + (size_t)K * (NOUT + 4) * sizeof(float);
    cudaFuncSetAttribute(k_gemm<NOUT, MODE, DUAL>,
                         cudaFuncAttributeMaxDynamicSharedMemorySize, (int)smem);
    k_gemm<NOUT, MODE, DUAL><<<(N + 63) / 64, 256, smem>>>(A, W, A2, W2, K, N, ep, C);
}

extern "C" void kernel_launch(void* const* d_in, const int* in_sizes, int n_in,
                              void* d_out, int out_size) {
    const float* x       = (const float*)d_in[0];
    const int*   ei      = (const int*)d_in[1];
    const float* ts      = (const float*)d_in[2];
    const float* mem     = (const float*)d_in[3];
    const float* W_in    = (const float*)d_in[4];
    const float* b_in    = (const float*)d_in[5];
    const float* W_time  = (const float*)d_in[6];
    const float* b_time  = (const float*)d_in[7];
    const float* W_ih    = (const float*)d_in[8];
    const float* W_hh    = (const float*)d_in[9];
    const float* b_ih    = (const float*)d_in[10];
    const float* b_hh    = (const float*)d_in[11];
    const float* W_gr    = (const float*)d_in[12];
    const float* b_gr    = (const float*)d_in[13];
    const float* W_gh    = (const float*)d_in[14];
    const float* b_gh    = (const float*)d_in[15];
    const float* ln_pa_g = (const float*)d_in[16];
    const float* ln_pa_b = (const float*)d_in[17];
    const float* Wv      = (const float*)d_in[18];
    const float* bv      = (const float*)d_in[19];
    const float* Wo      = (const float*)d_in[20];
    const float* bo      = (const float*)d_in[21];
    const float* ln_at_g = (const float*)d_in[22];
    const float* ln_at_b = (const float*)d_in[23];
    const float* W1      = (const float*)d_in[24];
    const float* b1      = (const float*)d_in[25];
    const float* W2p     = (const float*)d_in[26];
    const float* b2      = (const float*)d_in[27];

    const int E = in_sizes[2];
    const int N = in_sizes[0] / F;
    float* out_logits = (float*)d_out;
    float* out_mem = (float*)d_out + (size_t)2 * N;

    float *p_h, *p_r, *p_z, *p_hc, *p_hlrec, *p_hlhis, *p_h2, *p_v, *p_ao, *p_h3, *p_cls, *p_nt;
    unsigned char* p_upd;
    cudaGetSymbolAddress((void**)&p_h, g_h);
    cudaGetSymbolAddress((void**)&p_r, g_r);
    cudaGetSymbolAddress((void**)&p_z, g_z);
    cudaGetSymbolAddress((void**)&p_hc, g_hc);
    cudaGetSymbolAddress((void**)&p_hlrec, g_hlrec);
    cudaGetSymbolAddress((void**)&p_hlhis, g_hlhis);
    cudaGetSymbolAddress((void**)&p_h2, g_h2);
    cudaGetSymbolAddress((void**)&p_v, g_v);
    cudaGetSymbolAddress((void**)&p_ao, g_ao);
    cudaGetSymbolAddress((void**)&p_h3, g_h3);
    cudaGetSymbolAddress((void**)&p_cls, g_cls);
    cudaGetSymbolAddress((void**)&p_nt, g_nt);
    cudaGetSymbolAddress((void**)&p_upd, g_upd);

    const u32 k0 = (u32)((E - 1) / 2);
    const u32 k1 = (u32)(E / 2);
    const int EB = (E + 255) / 256;
    const int NB1024 = (N + 1023) / 1024;
    const int NWB = (N * 32 + 255) / 256;   // warp-per-node grids

    // ---- scalar / graph preprocessing ----
    k_init<<<256, 256>>>(N);
    k_edge1<<<EB, 256>>>(ei, ts, E);
    k_minmax<<<256, 256>>>(N);
    k_select<<<1, 256>>>(0, k0, -1, 2);
    k_select<<<1, 256>>>(0, k1, -1, 4);
    k_hist2<<<EB, 256>>>(ts, E);
    k_select<<<1, 256>>>(1, 0, 3, 6);
    k_select<<<1, 256>>>(2, 0, 5, 8);
    k_med<<<1, 1>>>();
    k_deg<<<EB, 256>>>(ei, ts, E);
    k_scan1<<<NB1024, 1024>>>(N);
    k_scan2<<<1, 1>>>(NB1024);
    k_scan3<<<(N + 255) / 256, 256>>>(N);
    k_fill<<<EB, 256>>>(ei, ts, E);

    // ---- h = relu(x@W_in^T + b_in + nt*W_time + b_time) + memory ----
    {
        Epi ep{}; ep.bias = b_in; ep.bias2 = b_time; ep.wtime = W_time; ep.mem = mem; ep.nt = p_nt;
        gemm_launch<H, 4, false>(x, W_in, nullptr, nullptr, F, N, ep, p_h);
    }
    // ---- GRU gates ----
    {
        Epi ep{}; ep.bias = b_ih; ep.bias2 = b_hh;
        gemm_launch<H, 3, true>(p_h, W_ih, mem, W_hh, H, N, ep, p_r);
    }
    {
        Epi ep{}; ep.bias = b_ih + H; ep.bias2 = b_hh + H;
        gemm_launch<H, 3, true>(p_h, W_ih + H * H, mem, W_hh + H * H, H, N, ep, p_z);
    }
    {
        Epi ep{}; ep.bias = b_hh + 2 * H;
        gemm_launch<H, 1, false>(mem, W_hh + 2 * H * H, nullptr, nullptr, H, N, ep, p_hc);
    }
    {
        Epi ep{}; ep.bias = b_ih + 2 * H; ep.ex1 = p_hc; ep.ex2 = p_r; ep.ex3 = p_z;
        ep.mem = mem; ep.upd = p_upd;
        gemm_launch<H, 5, false>(p_h, W_ih + 2 * H * H, nullptr, nullptr, H, N, ep, out_mem);
    }
    // ---- GCN linears + gather + path aggregation ----
    {
        Epi ep{};
        gemm_launch<H, 0, false>(p_h, W_gr, nullptr, nullptr, H, N, ep, p_hlrec);
        gemm_launch<H, 0, false>(p_h, W_gh, nullptr, nullptr, H, N, ep, p_hlhis);
    }
    k_gather<<<NWB, 256>>>(N, b_gr, b_gh);
    k_pathagg<<<NWB, 256>>>(N, ln_pa_g, ln_pa_b);
    // ---- attention (degenerate) + LN ----
    {
        Epi ep{}; ep.bias = bv;
        gemm_launch<H, 1, false>(p_h2, Wv, nullptr, nullptr, H, N, ep, p_v);
    }
    {
        Epi ep{}; ep.bias = bo; ep.ex1 = p_h2;
        gemm_launch<H, 6, false>(p_v, Wo, nullptr, nullptr, H, N, ep, p_ao);
    }
    k_ln<<<NWB, 256>>>(N, ln_at_g, ln_at_b);
    // ---- classifier ----
    {
        Epi ep{}; ep.bias = b1;
        gemm_launch<64, 2, false>(p_h3, W1, nullptr, nullptr, H, N, ep, p_cls);
    }
    k_logits<<<NWB, 256>>>(N, W2p, b2, out_logits);
}